// round 12
// baseline (speedup 1.0000x reference)
#include <cuda_runtime.h>
#include <cuda_fp16.h>
#include <stdint.h>

#define T_  128
#define B_  1024
#define D_  96
#define H_  128
#define BH  (B_ * H_)      // 131072
#define NSL 129

#define BETA   0.9f
#define THRESH 0.5f

// C[t] = x_t @ W_in^T stored at slice t+1 (slice 0 unused)
__device__ float g_P[(size_t)NSL * BH];           // ~67.6 MB
// layer-1 spikes as bits: [t][s][b][4 words of 32 h-bits]
__device__ uint16_t g_S[(size_t)T_ * 7 * B_ * 8]; // 14.7 MB

#define SPK_STR   272
#define SPK_BYTES 17408
#define W_BYTES   (128 * SPK_STR)
// precomputed fp16 2-term split of Wh0, exact smem image (2 terms)
__device__ __align__(16) uint8_t g_Wh16[2 * W_BYTES];

// ---------------------------------------------------------------------------
// Kernel 1: C = X @ W_in^T  (unchanged)
// ---------------------------------------------------------------------------
__global__ void __launch_bounds__(512, 2)
k_gemm_in(const float* __restrict__ x, const float* __restrict__ Win) {
    extern __shared__ float sm[];
    float* Ws  = sm;                 // [96][132]
    float* At  = sm + 96 * 132;      // [96][132]
    const int tid  = threadIdx.x;
    const int row0 = blockIdx.x * 128;

    for (int idx = tid; idx < H_ * D_; idx += 512) {
        int h = idx / D_, k = idx - h * D_;
        Ws[k * 132 + h] = Win[idx];
    }
    for (int idx = tid; idx < 128 * D_; idx += 512) {
        int r = idx / D_, k = idx - r * D_;
        At[k * 132 + r] = x[(size_t)row0 * D_ + idx];
    }
    __syncthreads();

    const int tx = tid & 31, ty = tid >> 5;
    const int r0 = ty * 8;
    const int c0 = tx * 4;
    float acc[8][4] = {};
    #pragma unroll 2
    for (int k = 0; k < D_; ++k) {
        const float4 w  = *(const float4*)(Ws + k * 132 + c0);
        const float4 aA = *(const float4*)(At + k * 132 + r0);
        const float4 aB = *(const float4*)(At + k * 132 + r0 + 4);
        const float av[8] = {aA.x, aA.y, aA.z, aA.w, aB.x, aB.y, aB.z, aB.w};
        #pragma unroll
        for (int i = 0; i < 8; ++i) {
            acc[i][0] = fmaf(av[i], w.x, acc[i][0]);
            acc[i][1] = fmaf(av[i], w.y, acc[i][1]);
            acc[i][2] = fmaf(av[i], w.z, acc[i][2]);
            acc[i][3] = fmaf(av[i], w.w, acc[i][3]);
        }
    }
    #pragma unroll
    for (int i = 0; i < 8; ++i)
        *(float4*)(g_P + (size_t)BH + (size_t)(row0 + r0 + i) * H_ + c0) =
            make_float4(acc[i][0], acc[i][1], acc[i][2], acc[i][3]);
}

// ---------------------------------------------------------------------------
// Kernel 1b: one-shot fp16 2-term split of Wh0 into the exact smem image
// ---------------------------------------------------------------------------
__global__ void k_wsplit(const float* __restrict__ Wh0) {
    const int idx = blockIdx.x * 256 + threadIdx.x;   // 0..8191 (float2 units)
    const float2 wv = ((const float2*)Wh0)[idx];
    const int n = idx >> 6, k2 = idx & 63;
    __half hx1 = __float2half_rn(wv.x);
    __half hx2 = __float2half_rn(wv.x - __half2float(hx1));
    __half hy1 = __float2half_rn(wv.y);
    __half hy2 = __float2half_rn(wv.y - __half2float(hy1));
    const int off = n * SPK_STR + k2 * 4;
    *(__half2*)(g_Wh16 + 0 * W_BYTES + off) = __halves2half2(hx2, hy2);
    *(__half2*)(g_Wh16 + 1 * W_BYTES + off) = __halves2half2(hx1, hy1);
}

// ---------------------------------------------------------------------------
// Kernel 2: fused prefix + layer-1 with 4-deep LDG pipeline.
// Bit-identical arithmetic; only prefetch depth changed.
// ---------------------------------------------------------------------------
__global__ void __launch_bounds__(256, 4)
k_pl1() {
    extern __shared__ float ring[];               // [51][256]
    const int tid  = threadIdx.x;
    const int g    = blockIdx.x * 256 + tid;      // flat (b,h)
    const int b    = g >> 7;
    const int hw   = (g & 127) >> 5;              // u32 word index within row
    const int lane = tid & 31;
    uint32_t* Sp = (uint32_t*)g_S;

    float run = 0.f;
    ring[tid] = 0.f;                              // P[0] at slot 0
    float cbuf[4];
    #pragma unroll
    for (int i = 0; i < 4; ++i)
        cbuf[i] = g_P[(size_t)(1 + i) * BH + g];  // C[0..3]
    int pos_w    = 1;                             // (t+1) mod 51
    int pos_base = 0;                             // (t-49) mod 51 (valid t>=49)

    for (int t = 0; t < T_; ++t) {
        run += cbuf[t & 3];                       // P[t+1]
        if (t + 4 < T_) cbuf[t & 3] = g_P[(size_t)(t + 5) * BH + g];
        ring[pos_w * 256 + tid] = run;

        float m1 = 0.f;
        const size_t outBase = (((size_t)t * 7) * B_ + b) * 4 + hw;

        if (t >= 49) {
            int p = pos_base;
            float plo = ring[p * 256 + tid];
            #pragma unroll
            for (int s = 0; s < 7; ++s) {
                p += 7; if (p >= 51) p -= 51;
                float phi = ring[p * 256 + tid];
                float cur = phi - plo;
                m1 = (m1 > THRESH) ? 0.f : fmaf(BETA, m1, cur);
                uint32_t bal = __ballot_sync(0xffffffffu, m1 > THRESH);
                if (lane == 0) Sp[outBase + (size_t)s * B_ * 4] = bal;
                plo = phi;
            }
            pos_base += 1; if (pos_base >= 51) pos_base -= 51;
        } else {
            #pragma unroll
            for (int s = 0; s < 7; ++s) {
                int j0 = 7 * s; if (j0 < 1) j0 = 1;
                int j1 = 7 * s + 6; if (j1 > t + 1) j1 = t + 1;
                int lo = j0 - 1;
                int hi = (j1 >= j0) ? j1 : lo;    // indices <= 50: no wrap
                float cur = ring[hi * 256 + tid] - ring[lo * 256 + tid];
                m1 = (m1 > THRESH) ? 0.f : fmaf(BETA, m1, cur);
                uint32_t bal = __ballot_sync(0xffffffffu, m1 > THRESH);
                if (lane == 0) Sp[outBase + (size_t)s * B_ * 4] = bal;
            }
        }
        pos_w += 1; if (pos_w >= 51) pos_w -= 51;
    }
}

// ---------------------------------------------------------------------------
// Kernel 3: hidden GEMM + layer 2 + output (R11 structure; prologue now a
// plain copy of the precomputed W image).
// ---------------------------------------------------------------------------
#define SM_SPK0   0
#define SM_SPK1   17408
#define SM_W      34816
#define SM_WOUT   104448
#define SM_MOUT   105472
#define SM_SRED   105984
#define SM_TOTAL  110080

__device__ __forceinline__ uint32_t s2u(const void* p) {
    uint32_t a;
    asm("{ .reg .u64 t; cvta.to.shared.u64 t, %1; cvt.u32.u64 %0, t; }"
        : "=r"(a) : "l"(p));
    return a;
}

__device__ __forceinline__ void ldm4(uint32_t* r, uint32_t addr) {
    asm volatile("ldmatrix.sync.aligned.m8n8.x4.shared.b16 {%0,%1,%2,%3}, [%4];"
        : "=r"(r[0]), "=r"(r[1]), "=r"(r[2]), "=r"(r[3]) : "r"(addr));
}

__device__ __forceinline__ void mma16816(float* d, const uint32_t* a,
                                         uint32_t b0, uint32_t b1) {
    asm("mma.sync.aligned.m16n8k16.row.col.f32.f16.f16.f32 "
        "{%0,%1,%2,%3}, {%4,%5,%6,%7}, {%8,%9}, {%0,%1,%2,%3};"
        : "+f"(d[0]), "+f"(d[1]), "+f"(d[2]), "+f"(d[3])
        : "r"(a[0]), "r"(a[1]), "r"(a[2]), "r"(a[3]), "r"(b0), "r"(b1));
}

__global__ void __launch_bounds__(256, 2)
k_snn_b(const float* __restrict__ Wout,
        const float* __restrict__ vx, const float* __restrict__ vy,
        float* __restrict__ out)
{
    extern __shared__ char smc[];
    const uint32_t smb = s2u(smc);
    float* sWout  = (float*)(smc + SM_WOUT);
    float* memout = (float*)(smc + SM_MOUT);

    const int tid  = threadIdx.x;
    const int w    = tid >> 5;
    const int lane = tid & 31;
    const int mg   = w & 1;
    const int ng   = w >> 1;
    const int t    = blockIdx.x >> 4;
    const int b0   = (blockIdx.x & 15) << 6;

    // ---- copy precomputed W image (2 terms, 69632 B) ----
    {
        const uint4* src = (const uint4*)g_Wh16;
        uint4* dst = (uint4*)(smc + SM_W);
        #pragma unroll
        for (int i = 0; i < 17; ++i)
            dst[i * 256 + tid] = src[i * 256 + tid];
    }
    sWout[tid] = Wout[tid];
    if (tid < 128) memout[tid] = 0.f;

    // ---- prefetch all 7 spike words ----
    const int wq = tid >> 6;
    const int re = tid & 63;
    uint32_t spw[7];
    {
        const uint32_t* Sp = (const uint32_t*)g_S;
        #pragma unroll
        for (int s = 0; s < 7; ++s)
            spw[s] = Sp[(((size_t)t * 7 + s) * B_ + b0 + re) * 4 + wq];
    }

    float mem2[2][4][4];
    #pragma unroll
    for (int mt = 0; mt < 2; ++mt)
        #pragma unroll
        for (int nt = 0; nt < 4; ++nt)
            #pragma unroll
            for (int e = 0; e < 4; ++e) mem2[mt][nt][e] = 0.f;

    const int r00 = 32 * mg + (lane >> 2);
    const int cb  = 32 * ng + 2 * (lane & 3);
    const uint32_t aLd0 = smb + SM_SPK0 + (32 * mg + (lane & 15)) * SPK_STR
                        + ((lane >> 4) << 4);
    const uint32_t bLdBase = smb + SM_W + (32 * ng + (lane & 15)) * SPK_STR
                           + ((lane >> 4) << 4);
    const uint32_t expDst0 = smb + SM_SPK0 + re * SPK_STR + wq * 64;

    // ---- expand step 0 into buffer 0 ----
    {
        const uint32_t bits = spw[0];
        uint32_t hv[16];
        #pragma unroll
        for (int j = 0; j < 16; ++j)
            hv[j] = ((bits >> (2*j)) & 1u ? 0x3C00u : 0u)
                  | ((bits >> (2*j+1)) & 1u ? 0x3C000000u : 0u);
        #pragma unroll
        for (int q = 0; q < 4; ++q)
            *(uint4*)(smc + SM_SPK0 + re * SPK_STR + wq * 64 + 16 * q) =
                make_uint4(hv[4*q], hv[4*q+1], hv[4*q+2], hv[4*q+3]);
    }
    __syncthreads();

    for (int s = 0; s < 7; ++s) {
        const uint32_t aLdBase = aLd0 + (uint32_t)(s & 1) * SPK_BYTES;

        float acc[2][4][4];
        #pragma unroll
        for (int mt = 0; mt < 2; ++mt)
            #pragma unroll
            for (int nt = 0; nt < 4; ++nt)
                #pragma unroll
                for (int e = 0; e < 4; ++e) acc[mt][nt][e] = 0.f;

        // ---- Phase A: n-rows 0..15 (nt 0,1) ----
        #pragma unroll
        for (int ks = 0; ks < 8; ++ks) {
            uint32_t a[2][4];
            #pragma unroll
            for (int mt = 0; mt < 2; ++mt)
                ldm4(a[mt], aLdBase + mt * (16 * SPK_STR) + ks * 32);
            #pragma unroll
            for (int term = 0; term < 2; ++term) {
                uint32_t br[4];
                ldm4(br, bLdBase + term * W_BYTES + ks * 32);
                #pragma unroll
                for (int mt = 0; mt < 2; ++mt) {
                    mma16816(acc[mt][0], a[mt], br[0], br[2]);
                    mma16816(acc[mt][1], a[mt], br[1], br[3]);
                }
            }
        }

        // ---- expand step s+1 into the other buffer ----
        if (s < 6) {
            const uint32_t bits = spw[s + 1];
            uint32_t hv[16];
            #pragma unroll
            for (int j = 0; j < 16; ++j)
                hv[j] = ((bits >> (2*j)) & 1u ? 0x3C00u : 0u)
                      | ((bits >> (2*j+1)) & 1u ? 0x3C000000u : 0u);
            char* dstp = smc + (expDst0 - smb) + ((s + 1) & 1) * SPK_BYTES;
            #pragma unroll
            for (int q = 0; q < 4; ++q)
                *(uint4*)(dstp + 16 * q) = make_uint4(hv[4*q], hv[4*q+1],
                                                      hv[4*q+2], hv[4*q+3]);
        }

        // ---- epilogue A (nt 0,1) ----
        float sred_p[2][2][2];
        #pragma unroll
        for (int mt = 0; mt < 2; ++mt)
            #pragma unroll
            for (int h = 0; h < 2; ++h)
                sred_p[mt][h][0] = sred_p[mt][h][1] = 0.f;

        #pragma unroll
        for (int nt = 0; nt < 2; ++nt) {
            const int c = cb + 8 * nt;
            const float2 w0 = *(const float2*)(sWout + c);
            const float2 w1 = *(const float2*)(sWout + 128 + c);
            #pragma unroll
            for (int mt = 0; mt < 2; ++mt)
                #pragma unroll
                for (int e = 0; e < 4; ++e) {
                    const int h = e >> 1;
                    float m  = mem2[mt][nt][e];
                    float nm = (m > THRESH) ? 0.f : fmaf(BETA, m, acc[mt][nt][e]);
                    mem2[mt][nt][e] = nm;
                    float sp = (nm > THRESH) ? 1.f : 0.f;
                    float wa = (e & 1) ? w0.y : w0.x;
                    float wb = (e & 1) ? w1.y : w1.x;
                    sred_p[mt][h][0] = fmaf(sp, wa, sred_p[mt][h][0]);
                    sred_p[mt][h][1] = fmaf(sp, wb, sred_p[mt][h][1]);
                }
        }

        // ---- Phase B: n-rows 16..31 (nt 2,3) ----
        #pragma unroll
        for (int ks = 0; ks < 8; ++ks) {
            uint32_t a[2][4];
            #pragma unroll
            for (int mt = 0; mt < 2; ++mt)
                ldm4(a[mt], aLdBase + mt * (16 * SPK_STR) + ks * 32);
            #pragma unroll
            for (int term = 0; term < 2; ++term) {
                uint32_t br[4];
                ldm4(br, bLdBase + term * W_BYTES + 16 * SPK_STR + ks * 32);
                #pragma unroll
                for (int mt = 0; mt < 2; ++mt) {
                    mma16816(acc[mt][2], a[mt], br[0], br[2]);
                    mma16816(acc[mt][3], a[mt], br[1], br[3]);
                }
            }
        }

        // ---- epilogue B (nt 2,3) ----
        #pragma unroll
        for (int nt = 2; nt < 4; ++nt) {
            const int c = cb + 8 * nt;
            const float2 w0 = *(const float2*)(sWout + c);
            const float2 w1 = *(const float2*)(sWout + 128 + c);
            #pragma unroll
            for (int mt = 0; mt < 2; ++mt)
                #pragma unroll
                for (int e = 0; e < 4; ++e) {
                    const int h = e >> 1;
                    float m  = mem2[mt][nt][e];
                    float nm = (m > THRESH) ? 0.f : fmaf(BETA, m, acc[mt][nt][e]);
                    mem2[mt][nt][e] = nm;
                    float sp = (nm > THRESH) ? 1.f : 0.f;
                    float wa = (e & 1) ? w0.y : w0.x;
                    float wb = (e & 1) ? w1.y : w1.x;
                    sred_p[mt][h][0] = fmaf(sp, wa, sred_p[mt][h][0]);
                    sred_p[mt][h][1] = fmaf(sp, wb, sred_p[mt][h][1]);
                }
        }

        #pragma unroll
        for (int mt = 0; mt < 2; ++mt)
            #pragma unroll
            for (int h = 0; h < 2; ++h)
                #pragma unroll
                for (int o = 0; o < 2; ++o) {
                    float v = sred_p[mt][h][o];
                    v += __shfl_xor_sync(0xffffffffu, v, 1);
                    v += __shfl_xor_sync(0xffffffffu, v, 2);
                    sred_p[mt][h][o] = v;
                }
        char* sredBuf = smc + SM_SRED + (s & 1) * 2048;
        if ((lane & 3) == 0) {
            #pragma unroll
            for (int mt = 0; mt < 2; ++mt)
                #pragma unroll
                for (int h = 0; h < 2; ++h) {
                    const int row = r00 + 16 * mt + 8 * h;
                    *(float*)(sredBuf + ((row * 2 + 0) * 4 + ng) * 4) = sred_p[mt][h][0];
                    *(float*)(sredBuf + ((row * 2 + 1) * 4 + ng) * 4) = sred_p[mt][h][1];
                }
        }
        __syncthreads();

        if (tid < 128) {
            const float4 v = *(const float4*)(sredBuf + tid * 16);
            float sum = (v.x + v.y) + (v.z + v.w);
            memout[tid] = fmaf(BETA, memout[tid], sum);
        }
    }

    // ---- epilogue ----
    if (tid < 128) {
        const int row = tid >> 1, o = tid & 1;
        const float v = o ? vy[0] : vx[0];
        out[((size_t)t * B_ + b0 + row) * 2 + o] = memout[tid] * v;
    }
}

// ---------------------------------------------------------------------------
extern "C" void kernel_launch(void* const* d_in, const int* in_sizes, int n_in,
                              void* d_out, int out_size) {
    const float* x    = (const float*)d_in[0];
    const float* Win  = (const float*)d_in[1];
    const float* Wh0  = (const float*)d_in[2];
    const float* Wout = (const float*)d_in[3];
    const float* vx   = (const float*)d_in[4];
    const float* vy   = (const float*)d_in[5];
    float* out = (float*)d_out;

    const int smem1 = (96 * 132 + 96 * 132) * 4;   // 101376 B
    const int smem2 = 51 * 256 * 4;                // 52224 B
    cudaFuncSetAttribute(k_gemm_in, cudaFuncAttributeMaxDynamicSharedMemorySize, smem1);
    cudaFuncSetAttribute(k_pl1,     cudaFuncAttributeMaxDynamicSharedMemorySize, smem2);
    cudaFuncSetAttribute(k_snn_b,   cudaFuncAttributeMaxDynamicSharedMemorySize, SM_TOTAL);

    k_gemm_in<<<(T_ * B_) / 128, 512, smem1>>>(x, Win);
    k_wsplit<<<32, 256>>>(Wh0);
    k_pl1<<<BH / 256, 256, smem2>>>();
    k_snn_b<<<T_ * 16, 256, SM_TOTAL>>>(Wout, vx, vy, out);
}

// round 13
// speedup vs baseline: 1.1363x; 1.1363x over previous
#include <cuda_runtime.h>
#include <cuda_fp16.h>
#include <stdint.h>

#define T_  128
#define B_  1024
#define D_  96
#define H_  128
#define BH  (B_ * H_)      // 131072
#define NSL 129

#define BETA   0.9f
#define THRESH 0.5f

// C[t] = x_t @ W_in^T stored at slice t+1 (slice 0 unused)
__device__ float g_P[(size_t)NSL * BH];           // ~67.6 MB
// layer-1 spikes as bits: [t][s][b][4 words of 32 h-bits]
__device__ uint16_t g_S[(size_t)T_ * 7 * B_ * 8]; // 14.7 MB

#define SPK_STR   272
#define SPK_BYTES 17408
#define W_BYTES   (128 * SPK_STR)
// precomputed fp16 2-term split of Wh0, exact smem image (2 terms)
__device__ __align__(16) uint8_t g_Wh16[2 * W_BYTES];

// ---------------------------------------------------------------------------
// Kernel 1: C = X @ W_in^T  (at FFMA roofline; unchanged)
// ---------------------------------------------------------------------------
__global__ void __launch_bounds__(512, 2)
k_gemm_in(const float* __restrict__ x, const float* __restrict__ Win) {
    extern __shared__ float sm[];
    float* Ws  = sm;                 // [96][132]
    float* At  = sm + 96 * 132;      // [96][132]
    const int tid  = threadIdx.x;
    const int row0 = blockIdx.x * 128;

    for (int idx = tid; idx < H_ * D_; idx += 512) {
        int h = idx / D_, k = idx - h * D_;
        Ws[k * 132 + h] = Win[idx];
    }
    for (int idx = tid; idx < 128 * D_; idx += 512) {
        int r = idx / D_, k = idx - r * D_;
        At[k * 132 + r] = x[(size_t)row0 * D_ + idx];
    }
    __syncthreads();

    const int tx = tid & 31, ty = tid >> 5;
    const int r0 = ty * 8;
    const int c0 = tx * 4;
    float acc[8][4] = {};
    #pragma unroll 2
    for (int k = 0; k < D_; ++k) {
        const float4 w  = *(const float4*)(Ws + k * 132 + c0);
        const float4 aA = *(const float4*)(At + k * 132 + r0);
        const float4 aB = *(const float4*)(At + k * 132 + r0 + 4);
        const float av[8] = {aA.x, aA.y, aA.z, aA.w, aB.x, aB.y, aB.z, aB.w};
        #pragma unroll
        for (int i = 0; i < 8; ++i) {
            acc[i][0] = fmaf(av[i], w.x, acc[i][0]);
            acc[i][1] = fmaf(av[i], w.y, acc[i][1]);
            acc[i][2] = fmaf(av[i], w.z, acc[i][2]);
            acc[i][3] = fmaf(av[i], w.w, acc[i][3]);
        }
    }
    #pragma unroll
    for (int i = 0; i < 8; ++i)
        *(float4*)(g_P + (size_t)BH + (size_t)(row0 + r0 + i) * H_ + c0) =
            make_float4(acc[i][0], acc[i][1], acc[i][2], acc[i][3]);
}

// ---------------------------------------------------------------------------
// Kernel 1b: one-shot fp16 2-term split of Wh0 into the exact smem image
// ---------------------------------------------------------------------------
__global__ void k_wsplit(const float* __restrict__ Wh0) {
    const int idx = blockIdx.x * 256 + threadIdx.x;   // 0..8191 (float2 units)
    const float2 wv = ((const float2*)Wh0)[idx];
    const int n = idx >> 6, k2 = idx & 63;
    __half hx1 = __float2half_rn(wv.x);
    __half hx2 = __float2half_rn(wv.x - __half2float(hx1));
    __half hy1 = __float2half_rn(wv.y);
    __half hy2 = __float2half_rn(wv.y - __half2float(hy1));
    const int off = n * SPK_STR + k2 * 4;
    *(__half2*)(g_Wh16 + 0 * W_BYTES + off) = __halves2half2(hx2, hy2);
    *(__half2*)(g_Wh16 + 1 * W_BYTES + off) = __halves2half2(hx1, hy1);
}

// ---------------------------------------------------------------------------
// Kernel 2: fused prefix + layer-1, PHASE-SPLIT.
//  Phase 1: full 129-slice prefix column in smem (order-identical run sum).
//  Phase 2: window diffs + m1 recurrence, TWO independent t-chains
//           interleaved for ILP.  Bit-identical arithmetic.
// ---------------------------------------------------------------------------
__global__ void __launch_bounds__(128)
k_pl1() {
    extern __shared__ float ring[];               // [129][128]
    const int tid  = threadIdx.x;                 // 0..127
    const int g    = blockIdx.x * 128 + tid;      // flat (b,h)
    const int b    = g >> 7;
    const int hw   = (g & 127) >> 5;
    const int lane = tid & 31;
    uint32_t* Sp = (uint32_t*)g_S;

    // ---- Phase 1: full prefix (same accumulation order as before) ----
    float run = 0.f;
    ring[tid] = 0.f;
    float cb[4];
    #pragma unroll
    for (int i = 0; i < 4; ++i)
        cb[i] = g_P[(size_t)(1 + i) * BH + g];
    for (int t = 0; t < T_; ++t) {
        run += cb[t & 3];
        if (t + 4 < T_) cb[t & 3] = g_P[(size_t)(t + 5) * BH + g];
        ring[(t + 1) * 128 + tid] = run;
    }
    // each thread reads only its own column -> no barrier needed

    // ---- Phase 2: two independent t-chains per iteration ----
    for (int t = 0; t < T_; t += 2) {
        const int ta = t, tb = t + 1;
        float m1a = 0.f, m1b = 0.f;
        const size_t outA = (((size_t)ta * 7) * B_ + b) * 4 + hw;
        const size_t outB = (((size_t)tb * 7) * B_ + b) * 4 + hw;
        #pragma unroll
        for (int s = 0; s < 7; ++s) {
            int loa, hia, lob, hib;
            if (ta >= 49) { loa = ta - 49 + 7 * s; hia = loa + 7; }
            else {
                int j0 = 7 * s; if (j0 < 1) j0 = 1;
                int j1 = 7 * s + 6; if (j1 > ta + 1) j1 = ta + 1;
                loa = j0 - 1;
                hia = (j1 >= j0) ? j1 : loa;
            }
            if (tb >= 49) { lob = tb - 49 + 7 * s; hib = lob + 7; }
            else {
                int j0 = 7 * s; if (j0 < 1) j0 = 1;
                int j1 = 7 * s + 6; if (j1 > tb + 1) j1 = tb + 1;
                lob = j0 - 1;
                hib = (j1 >= j0) ? j1 : lob;
            }
            float cura = ring[hia * 128 + tid] - ring[loa * 128 + tid];
            float curb = ring[hib * 128 + tid] - ring[lob * 128 + tid];
            m1a = (m1a > THRESH) ? 0.f : fmaf(BETA, m1a, cura);
            m1b = (m1b > THRESH) ? 0.f : fmaf(BETA, m1b, curb);
            uint32_t ba = __ballot_sync(0xffffffffu, m1a > THRESH);
            uint32_t bb = __ballot_sync(0xffffffffu, m1b > THRESH);
            if (lane == 0) {
                Sp[outA + (size_t)s * B_ * 4] = ba;
                Sp[outB + (size_t)s * B_ * 4] = bb;
            }
        }
    }
}

// ---------------------------------------------------------------------------
// Kernel 3: hidden GEMM + layer 2 + output.  R10 single-phase inner loop,
// precomputed W image, double-buffered spike tile, 1 barrier/step.
// ---------------------------------------------------------------------------
#define SM_SPK0   0
#define SM_SPK1   17408
#define SM_W      34816
#define SM_WOUT   104448
#define SM_MOUT   105472
#define SM_SRED   105984
#define SM_TOTAL  110080

__device__ __forceinline__ uint32_t s2u(const void* p) {
    uint32_t a;
    asm("{ .reg .u64 t; cvta.to.shared.u64 t, %1; cvt.u32.u64 %0, t; }"
        : "=r"(a) : "l"(p));
    return a;
}

__device__ __forceinline__ void ldm4(uint32_t* r, uint32_t addr) {
    asm volatile("ldmatrix.sync.aligned.m8n8.x4.shared.b16 {%0,%1,%2,%3}, [%4];"
        : "=r"(r[0]), "=r"(r[1]), "=r"(r[2]), "=r"(r[3]) : "r"(addr));
}

__device__ __forceinline__ void mma16816(float* d, const uint32_t* a,
                                         uint32_t b0, uint32_t b1) {
    asm("mma.sync.aligned.m16n8k16.row.col.f32.f16.f16.f32 "
        "{%0,%1,%2,%3}, {%4,%5,%6,%7}, {%8,%9}, {%0,%1,%2,%3};"
        : "+f"(d[0]), "+f"(d[1]), "+f"(d[2]), "+f"(d[3])
        : "r"(a[0]), "r"(a[1]), "r"(a[2]), "r"(a[3]), "r"(b0), "r"(b1));
}

__global__ void __launch_bounds__(256, 2)
k_snn_b(const float* __restrict__ Wout,
        const float* __restrict__ vx, const float* __restrict__ vy,
        float* __restrict__ out)
{
    extern __shared__ char smc[];
    const uint32_t smb = s2u(smc);
    float* sWout  = (float*)(smc + SM_WOUT);
    float* memout = (float*)(smc + SM_MOUT);

    const int tid  = threadIdx.x;
    const int w    = tid >> 5;
    const int lane = tid & 31;
    const int mg   = w & 1;
    const int ng   = w >> 1;
    const int t    = blockIdx.x >> 4;
    const int b0   = (blockIdx.x & 15) << 6;

    // ---- copy precomputed W image (2 terms, 69632 B) ----
    {
        const uint4* src = (const uint4*)g_Wh16;
        uint4* dst = (uint4*)(smc + SM_W);
        #pragma unroll
        for (int i = 0; i < 17; ++i)
            dst[i * 256 + tid] = src[i * 256 + tid];
    }
    sWout[tid] = Wout[tid];
    if (tid < 128) memout[tid] = 0.f;

    // ---- prefetch all 7 spike words ----
    const int wq = tid >> 6;
    const int re = tid & 63;
    uint32_t spw[7];
    {
        const uint32_t* Sp = (const uint32_t*)g_S;
        #pragma unroll
        for (int s = 0; s < 7; ++s)
            spw[s] = Sp[(((size_t)t * 7 + s) * B_ + b0 + re) * 4 + wq];
    }

    float mem2[2][4][4];
    #pragma unroll
    for (int mt = 0; mt < 2; ++mt)
        #pragma unroll
        for (int nt = 0; nt < 4; ++nt)
            #pragma unroll
            for (int e = 0; e < 4; ++e) mem2[mt][nt][e] = 0.f;

    const int r00 = 32 * mg + (lane >> 2);
    const int cb  = 32 * ng + 2 * (lane & 3);
    const uint32_t aLd0 = smb + SM_SPK0 + (32 * mg + (lane & 15)) * SPK_STR
                        + ((lane >> 4) << 4);
    const uint32_t bLdBase = smb + SM_W + (32 * ng + (lane & 15)) * SPK_STR
                           + ((lane >> 4) << 4);
    const uint32_t expDst0 = smb + SM_SPK0 + re * SPK_STR + wq * 64;

    // ---- expand step 0 into buffer 0 ----
    {
        const uint32_t bits = spw[0];
        uint32_t hv[16];
        #pragma unroll
        for (int j = 0; j < 16; ++j)
            hv[j] = ((bits >> (2*j)) & 1u ? 0x3C00u : 0u)
                  | ((bits >> (2*j+1)) & 1u ? 0x3C000000u : 0u);
        #pragma unroll
        for (int q = 0; q < 4; ++q)
            *(uint4*)(smc + SM_SPK0 + re * SPK_STR + wq * 64 + 16 * q) =
                make_uint4(hv[4*q], hv[4*q+1], hv[4*q+2], hv[4*q+3]);
    }
    __syncthreads();

    for (int s = 0; s < 7; ++s) {
        const uint32_t aLdBase = aLd0 + (uint32_t)(s & 1) * SPK_BYTES;

        float acc[2][4][4];
        #pragma unroll
        for (int mt = 0; mt < 2; ++mt)
            #pragma unroll
            for (int nt = 0; nt < 4; ++nt)
                #pragma unroll
                for (int e = 0; e < 4; ++e) acc[mt][nt][e] = 0.f;

        // ---- hidden GEMM: acc = spk @ (Wlo + Whi)^T ----
        #pragma unroll
        for (int ks = 0; ks < 8; ++ks) {
            uint32_t a[2][4];
            #pragma unroll
            for (int mt = 0; mt < 2; ++mt)
                ldm4(a[mt], aLdBase + mt * (16 * SPK_STR) + ks * 32);
            #pragma unroll
            for (int term = 0; term < 2; ++term) {
                uint32_t b0r[4], b1r[4];
                ldm4(b0r, bLdBase + term * W_BYTES + ks * 32);
                ldm4(b1r, bLdBase + term * W_BYTES + 16 * SPK_STR + ks * 32);
                #pragma unroll
                for (int mt = 0; mt < 2; ++mt) {
                    mma16816(acc[mt][0], a[mt], b0r[0], b0r[2]);
                    mma16816(acc[mt][1], a[mt], b0r[1], b0r[3]);
                    mma16816(acc[mt][2], a[mt], b1r[0], b1r[2]);
                    mma16816(acc[mt][3], a[mt], b1r[1], b1r[3]);
                }
            }
        }

        // ---- expand step s+1 into the other buffer ----
        if (s < 6) {
            const uint32_t bits = spw[s + 1];
            uint32_t hv[16];
            #pragma unroll
            for (int j = 0; j < 16; ++j)
                hv[j] = ((bits >> (2*j)) & 1u ? 0x3C00u : 0u)
                      | ((bits >> (2*j+1)) & 1u ? 0x3C000000u : 0u);
            char* dstp = smc + (expDst0 - smb) + ((s + 1) & 1) * SPK_BYTES;
            #pragma unroll
            for (int q = 0; q < 4; ++q)
                *(uint4*)(dstp + 16 * q) = make_uint4(hv[4*q], hv[4*q+1],
                                                      hv[4*q+2], hv[4*q+3]);
        }

        // ---- layer 2 + output projection partials ----
        float sred_p[2][2][2];
        #pragma unroll
        for (int mt = 0; mt < 2; ++mt)
            #pragma unroll
            for (int h = 0; h < 2; ++h)
                sred_p[mt][h][0] = sred_p[mt][h][1] = 0.f;

        #pragma unroll
        for (int nt = 0; nt < 4; ++nt) {
            const int c = cb + 8 * nt;
            const float2 w0 = *(const float2*)(sWout + c);
            const float2 w1 = *(const float2*)(sWout + 128 + c);
            #pragma unroll
            for (int mt = 0; mt < 2; ++mt)
                #pragma unroll
                for (int e = 0; e < 4; ++e) {
                    const int h = e >> 1;
                    float m  = mem2[mt][nt][e];
                    float nm = (m > THRESH) ? 0.f : fmaf(BETA, m, acc[mt][nt][e]);
                    mem2[mt][nt][e] = nm;
                    float sp = (nm > THRESH) ? 1.f : 0.f;
                    float wa = (e & 1) ? w0.y : w0.x;
                    float wb = (e & 1) ? w1.y : w1.x;
                    sred_p[mt][h][0] = fmaf(sp, wa, sred_p[mt][h][0]);
                    sred_p[mt][h][1] = fmaf(sp, wb, sred_p[mt][h][1]);
                }
        }
        #pragma unroll
        for (int mt = 0; mt < 2; ++mt)
            #pragma unroll
            for (int h = 0; h < 2; ++h)
                #pragma unroll
                for (int o = 0; o < 2; ++o) {
                    float v = sred_p[mt][h][o];
                    v += __shfl_xor_sync(0xffffffffu, v, 1);
                    v += __shfl_xor_sync(0xffffffffu, v, 2);
                    sred_p[mt][h][o] = v;
                }
        char* sredBuf = smc + SM_SRED + (s & 1) * 2048;
        if ((lane & 3) == 0) {
            #pragma unroll
            for (int mt = 0; mt < 2; ++mt)
                #pragma unroll
                for (int h = 0; h < 2; ++h) {
                    const int row = r00 + 16 * mt + 8 * h;
                    *(float*)(sredBuf + ((row * 2 + 0) * 4 + ng) * 4) = sred_p[mt][h][0];
                    *(float*)(sredBuf + ((row * 2 + 1) * 4 + ng) * 4) = sred_p[mt][h][1];
                }
        }
        __syncthreads();

        if (tid < 128) {
            const float4 v = *(const float4*)(sredBuf + tid * 16);
            float sum = (v.x + v.y) + (v.z + v.w);
            memout[tid] = fmaf(BETA, memout[tid], sum);
        }
    }

    // ---- epilogue ----
    if (tid < 128) {
        const int row = tid >> 1, o = tid & 1;
        const float v = o ? vy[0] : vx[0];
        out[((size_t)t * B_ + b0 + row) * 2 + o] = memout[tid] * v;
    }
}

// ---------------------------------------------------------------------------
extern "C" void kernel_launch(void* const* d_in, const int* in_sizes, int n_in,
                              void* d_out, int out_size) {
    const float* x    = (const float*)d_in[0];
    const float* Win  = (const float*)d_in[1];
    const float* Wh0  = (const float*)d_in[2];
    const float* Wout = (const float*)d_in[3];
    const float* vx   = (const float*)d_in[4];
    const float* vy   = (const float*)d_in[5];
    float* out = (float*)d_out;

    const int smem1 = (96 * 132 + 96 * 132) * 4;   // 101376 B
    const int smem2 = 129 * 128 * 4;               // 66048 B
    cudaFuncSetAttribute(k_gemm_in, cudaFuncAttributeMaxDynamicSharedMemorySize, smem1);
    cudaFuncSetAttribute(k_pl1,     cudaFuncAttributeMaxDynamicSharedMemorySize, smem2);
    cudaFuncSetAttribute(k_snn_b,   cudaFuncAttributeMaxDynamicSharedMemorySize, SM_TOTAL);

    k_gemm_in<<<(T_ * B_) / 128, 512, smem1>>>(x, Win);
    k_wsplit<<<32, 256>>>(Wh0);
    k_pl1<<<BH / 128, 128, smem2>>>();
    k_snn_b<<<T_ * 16, 256, SM_TOTAL>>>(Wout, vx, vy, out);
}

// round 15
// speedup vs baseline: 1.1587x; 1.0197x over previous
#include <cuda_runtime.h>
#include <cuda_fp16.h>
#include <stdint.h>

#define T_  128
#define B_  1024
#define D_  96
#define H_  128
#define BH  (B_ * H_)      // 131072
#define NSL 129

#define BETA   0.9f
#define THRESH 0.5f

// C[t] = x_t @ W_in^T stored at slice t+1 (slice 0 unused)
__device__ float g_P[(size_t)NSL * BH];           // ~67.6 MB
// layer-1 spikes as bits: [t][s][b][4 words of 32 h-bits]
__device__ uint16_t g_S[(size_t)T_ * 7 * B_ * 8]; // 14.7 MB

#define SPK_STR   272
#define SPK_BYTES 17408
#define W_BYTES   (128 * SPK_STR)
// precomputed fp16 2-term split of Wh0, exact smem image (2 terms)
__device__ __align__(16) uint8_t g_Wh16[2 * W_BYTES];

__device__ __forceinline__ uint32_t pack_half2(__half lo, __half hi) {
    return (uint32_t)__half_as_ushort(lo) | ((uint32_t)__half_as_ushort(hi) << 16);
}

// ---------------------------------------------------------------------------
// Kernel 1: C = X @ W_in^T  (unchanged)
// ---------------------------------------------------------------------------
__global__ void __launch_bounds__(512, 2)
k_gemm_in(const float* __restrict__ x, const float* __restrict__ Win) {
    extern __shared__ float sm[];
    float* Ws  = sm;                 // [96][132]
    float* At  = sm + 96 * 132;      // [96][132]
    const int tid  = threadIdx.x;
    const int row0 = blockIdx.x * 128;

    for (int idx = tid; idx < H_ * D_; idx += 512) {
        int h = idx / D_, k = idx - h * D_;
        Ws[k * 132 + h] = Win[idx];
    }
    for (int idx = tid; idx < 128 * D_; idx += 512) {
        int r = idx / D_, k = idx - r * D_;
        At[k * 132 + r] = x[(size_t)row0 * D_ + idx];
    }
    __syncthreads();

    const int tx = tid & 31, ty = tid >> 5;
    const int r0 = ty * 8;
    const int c0 = tx * 4;
    float acc[8][4] = {};
    #pragma unroll 2
    for (int k = 0; k < D_; ++k) {
        const float4 w  = *(const float4*)(Ws + k * 132 + c0);
        const float4 aA = *(const float4*)(At + k * 132 + r0);
        const float4 aB = *(const float4*)(At + k * 132 + r0 + 4);
        const float av[8] = {aA.x, aA.y, aA.z, aA.w, aB.x, aB.y, aB.z, aB.w};
        #pragma unroll
        for (int i = 0; i < 8; ++i) {
            acc[i][0] = fmaf(av[i], w.x, acc[i][0]);
            acc[i][1] = fmaf(av[i], w.y, acc[i][1]);
            acc[i][2] = fmaf(av[i], w.z, acc[i][2]);
            acc[i][3] = fmaf(av[i], w.w, acc[i][3]);
        }
    }
    #pragma unroll
    for (int i = 0; i < 8; ++i)
        *(float4*)(g_P + (size_t)BH + (size_t)(row0 + r0 + i) * H_ + c0) =
            make_float4(acc[i][0], acc[i][1], acc[i][2], acc[i][3]);
}

// ---------------------------------------------------------------------------
// Kernel 1b: one-shot fp16 2-term split of Wh0 into the exact smem image
// ---------------------------------------------------------------------------
__global__ void k_wsplit(const float* __restrict__ Wh0) {
    const int idx = blockIdx.x * 256 + threadIdx.x;   // 0..8191 (float2 units)
    const float2 wv = ((const float2*)Wh0)[idx];
    const int n = idx >> 6, k2 = idx & 63;
    __half hx1 = __float2half_rn(wv.x);
    __half hx2 = __float2half_rn(wv.x - __half2float(hx1));
    __half hy1 = __float2half_rn(wv.y);
    __half hy2 = __float2half_rn(wv.y - __half2float(hy1));
    const int off = n * SPK_STR + k2 * 4;
    *(__half2*)(g_Wh16 + 0 * W_BYTES + off) = __halves2half2(hx2, hy2);
    *(__half2*)(g_Wh16 + 1 * W_BYTES + off) = __halves2half2(hx1, hy1);
}

// ---------------------------------------------------------------------------
// Kernel 2: fused prefix + layer-1 (phase-split, unchanged from R13)
// ---------------------------------------------------------------------------
__global__ void __launch_bounds__(128)
k_pl1() {
    extern __shared__ float ring[];               // [129][128]
    const int tid  = threadIdx.x;
    const int g    = blockIdx.x * 128 + tid;
    const int b    = g >> 7;
    const int hw   = (g & 127) >> 5;
    const int lane = tid & 31;
    uint32_t* Sp = (uint32_t*)g_S;

    float run = 0.f;
    ring[tid] = 0.f;
    float cb[4];
    #pragma unroll
    for (int i = 0; i < 4; ++i)
        cb[i] = g_P[(size_t)(1 + i) * BH + g];
    for (int t = 0; t < T_; ++t) {
        run += cb[t & 3];
        if (t + 4 < T_) cb[t & 3] = g_P[(size_t)(t + 5) * BH + g];
        ring[(t + 1) * 128 + tid] = run;
    }

    for (int t = 0; t < T_; t += 2) {
        const int ta = t, tb = t + 1;
        float m1a = 0.f, m1b = 0.f;
        const size_t outA = (((size_t)ta * 7) * B_ + b) * 4 + hw;
        const size_t outB = (((size_t)tb * 7) * B_ + b) * 4 + hw;
        #pragma unroll
        for (int s = 0; s < 7; ++s) {
            int loa, hia, lob, hib;
            if (ta >= 49) { loa = ta - 49 + 7 * s; hia = loa + 7; }
            else {
                int j0 = 7 * s; if (j0 < 1) j0 = 1;
                int j1 = 7 * s + 6; if (j1 > ta + 1) j1 = ta + 1;
                loa = j0 - 1;
                hia = (j1 >= j0) ? j1 : loa;
            }
            if (tb >= 49) { lob = tb - 49 + 7 * s; hib = lob + 7; }
            else {
                int j0 = 7 * s; if (j0 < 1) j0 = 1;
                int j1 = 7 * s + 6; if (j1 > tb + 1) j1 = tb + 1;
                lob = j0 - 1;
                hib = (j1 >= j0) ? j1 : lob;
            }
            float cura = ring[hia * 128 + tid] - ring[loa * 128 + tid];
            float curb = ring[hib * 128 + tid] - ring[lob * 128 + tid];
            m1a = (m1a > THRESH) ? 0.f : fmaf(BETA, m1a, cura);
            m1b = (m1b > THRESH) ? 0.f : fmaf(BETA, m1b, curb);
            uint32_t ba = __ballot_sync(0xffffffffu, m1a > THRESH);
            uint32_t bb = __ballot_sync(0xffffffffu, m1b > THRESH);
            if (lane == 0) {
                Sp[outA + (size_t)s * B_ * 4] = ba;
                Sp[outB + (size_t)s * B_ * 4] = bb;
            }
        }
    }
}

// ---------------------------------------------------------------------------
// Kernel 3: hidden GEMM + layer 2 + output.  Projection epilogue is now
// done with MMAs (C-fragment -> A-fragment reuse); no shuffles.
// ---------------------------------------------------------------------------
#define SM_SPK0   0
#define SM_SPK1   17408
#define SM_W      34816
#define SM_MOUT   104448                 // 512
#define SM_SRED   104960                 // 2 x 2048
#define SM_TOTAL  109056

__device__ __forceinline__ uint32_t s2u(const void* p) {
    uint32_t a;
    asm("{ .reg .u64 t; cvta.to.shared.u64 t, %1; cvt.u32.u64 %0, t; }"
        : "=r"(a) : "l"(p));
    return a;
}

__device__ __forceinline__ void ldm4(uint32_t* r, uint32_t addr) {
    asm volatile("ldmatrix.sync.aligned.m8n8.x4.shared.b16 {%0,%1,%2,%3}, [%4];"
        : "=r"(r[0]), "=r"(r[1]), "=r"(r[2]), "=r"(r[3]) : "r"(addr));
}

__device__ __forceinline__ void mma16816(float* d, const uint32_t* a,
                                         uint32_t b0, uint32_t b1) {
    asm("mma.sync.aligned.m16n8k16.row.col.f32.f16.f16.f32 "
        "{%0,%1,%2,%3}, {%4,%5,%6,%7}, {%8,%9}, {%0,%1,%2,%3};"
        : "+f"(d[0]), "+f"(d[1]), "+f"(d[2]), "+f"(d[3])
        : "r"(a[0]), "r"(a[1]), "r"(a[2]), "r"(a[3]), "r"(b0), "r"(b1));
}

__global__ void __launch_bounds__(256, 2)
k_snn_b(const float* __restrict__ Wout,
        const float* __restrict__ vx, const float* __restrict__ vy,
        float* __restrict__ out)
{
    extern __shared__ char smc[];
    const uint32_t smb = s2u(smc);
    float* memout = (float*)(smc + SM_MOUT);

    const int tid  = threadIdx.x;
    const int w    = tid >> 5;
    const int lane = tid & 31;
    const int mg   = w & 1;
    const int ng   = w >> 1;
    const int t    = blockIdx.x >> 4;
    const int b0   = (blockIdx.x & 15) << 6;

    // ---- copy precomputed W image (2 terms, 69632 B) ----
    {
        const uint4* src = (const uint4*)g_Wh16;
        uint4* dst = (uint4*)(smc + SM_W);
        #pragma unroll
        for (int i = 0; i < 17; ++i)
            dst[i * 256 + tid] = src[i * 256 + tid];
    }
    if (tid < 128) memout[tid] = 0.f;

    // ---- per-warp Wout B-fragments (2-term fp16 split), built once ----
    // bW[term][kt][j]: m16n8k16 B frag; k = warp cols [32ng+16kt, +16), n = 0,1
    uint32_t bW[2][2][2];
    {
        const int n   = lane >> 2;        // fragment n index
        const int tig = lane & 3;
        #pragma unroll
        for (int kt = 0; kt < 2; ++kt) {
            #pragma unroll
            for (int j = 0; j < 2; ++j) {
                const int k0 = 32 * ng + 16 * kt + 2 * tig + 8 * j;
                float w0 = (n < 2) ? Wout[n * 128 + k0]     : 0.f;
                float w1 = (n < 2) ? Wout[n * 128 + k0 + 1] : 0.f;
                __half h0 = __float2half_rn(w0);
                __half l0 = __float2half_rn(w0 - __half2float(h0));
                __half h1 = __float2half_rn(w1);
                __half l1 = __float2half_rn(w1 - __half2float(h1));
                bW[1][kt][j] = pack_half2(h0, h1); // hi term
                bW[0][kt][j] = pack_half2(l0, l1); // lo term
            }
        }
    }

    // ---- prefetch all 7 spike words ----
    const int wq = tid >> 6;
    const int re = tid & 63;
    uint32_t spw[7];
    {
        const uint32_t* Sp = (const uint32_t*)g_S;
        #pragma unroll
        for (int s = 0; s < 7; ++s)
            spw[s] = Sp[(((size_t)t * 7 + s) * B_ + b0 + re) * 4 + wq];
    }

    float mem2[2][4][4];
    #pragma unroll
    for (int mt = 0; mt < 2; ++mt)
        #pragma unroll
        for (int nt = 0; nt < 4; ++nt)
            #pragma unroll
            for (int e = 0; e < 4; ++e) mem2[mt][nt][e] = 0.f;

    const int r00 = 32 * mg + (lane >> 2);
    const uint32_t aLd0 = smb + SM_SPK0 + (32 * mg + (lane & 15)) * SPK_STR
                        + ((lane >> 4) << 4);
    const uint32_t bLdBase = smb + SM_W + (32 * ng + (lane & 15)) * SPK_STR
                           + ((lane >> 4) << 4);
    const uint32_t expDst0 = smb + SM_SPK0 + re * SPK_STR + wq * 64;

    // ---- expand step 0 into buffer 0 ----
    {
        const uint32_t bits = spw[0];
        uint32_t hv[16];
        #pragma unroll
        for (int j = 0; j < 16; ++j)
            hv[j] = ((bits >> (2*j)) & 1u ? 0x3C00u : 0u)
                  | ((bits >> (2*j+1)) & 1u ? 0x3C000000u : 0u);
        #pragma unroll
        for (int q = 0; q < 4; ++q)
            *(uint4*)(smc + SM_SPK0 + re * SPK_STR + wq * 64 + 16 * q) =
                make_uint4(hv[4*q], hv[4*q+1], hv[4*q+2], hv[4*q+3]);
    }
    __syncthreads();

    for (int s = 0; s < 7; ++s) {
        const uint32_t aLdBase = aLd0 + (uint32_t)(s & 1) * SPK_BYTES;

        float acc[2][4][4];
        #pragma unroll
        for (int mt = 0; mt < 2; ++mt)
            #pragma unroll
            for (int nt = 0; nt < 4; ++nt)
                #pragma unroll
                for (int e = 0; e < 4; ++e) acc[mt][nt][e] = 0.f;

        // ---- hidden GEMM: acc = spk @ (Wlo + Whi)^T ----
        #pragma unroll
        for (int ks = 0; ks < 8; ++ks) {
            uint32_t a[2][4];
            #pragma unroll
            for (int mt = 0; mt < 2; ++mt)
                ldm4(a[mt], aLdBase + mt * (16 * SPK_STR) + ks * 32);
            #pragma unroll
            for (int term = 0; term < 2; ++term) {
                uint32_t b0r[4], b1r[4];
                ldm4(b0r, bLdBase + term * W_BYTES + ks * 32);
                ldm4(b1r, bLdBase + term * W_BYTES + 16 * SPK_STR + ks * 32);
                #pragma unroll
                for (int mt = 0; mt < 2; ++mt) {
                    mma16816(acc[mt][0], a[mt], b0r[0], b0r[2]);
                    mma16816(acc[mt][1], a[mt], b0r[1], b0r[3]);
                    mma16816(acc[mt][2], a[mt], b1r[0], b1r[2]);
                    mma16816(acc[mt][3], a[mt], b1r[1], b1r[3]);
                }
            }
        }

        // ---- expand step s+1 into the other buffer ----
        if (s < 6) {
            const uint32_t bits = spw[s + 1];
            uint32_t hv[16];
            #pragma unroll
            for (int j = 0; j < 16; ++j)
                hv[j] = ((bits >> (2*j)) & 1u ? 0x3C00u : 0u)
                      | ((bits >> (2*j+1)) & 1u ? 0x3C000000u : 0u);
            char* dstp = smc + (expDst0 - smb) + ((s + 1) & 1) * SPK_BYTES;
            #pragma unroll
            for (int q = 0; q < 4; ++q)
                *(uint4*)(dstp + 16 * q) = make_uint4(hv[4*q], hv[4*q+1],
                                                      hv[4*q+2], hv[4*q+3]);
        }

        // ---- layer 2: mem2 recurrence + pack spikes as A-fragments ----
        uint32_t aF[2][2][4];   // [mt][kt][4]
        #pragma unroll
        for (int mt = 0; mt < 2; ++mt)
            #pragma unroll
            for (int nt = 0; nt < 4; ++nt) {
                float nm[4];
                #pragma unroll
                for (int e = 0; e < 4; ++e) {
                    float m = mem2[mt][nt][e];
                    nm[e] = (m > THRESH) ? 0.f : fmaf(BETA, m, acc[mt][nt][e]);
                    mem2[mt][nt][e] = nm[e];
                }
                uint32_t lo = (nm[0] > THRESH ? 0x3C00u : 0u)
                            | (nm[1] > THRESH ? 0x3C000000u : 0u);
                uint32_t hi = (nm[2] > THRESH ? 0x3C00u : 0u)
                            | (nm[3] > THRESH ? 0x3C000000u : 0u);
                const int kt = nt >> 1;
                const int oj = (nt & 1) ? 2 : 0;
                aF[mt][kt][oj]     = lo;   // (r,  k or k+8)
                aF[mt][kt][oj + 1] = hi;   // (r+8, same k)
            }

        // ---- projection via MMA:  proj = spk2 @ [Wout_lo; Wout_hi]^T ----
        float pacc[2][4];
        #pragma unroll
        for (int mt = 0; mt < 2; ++mt)
            #pragma unroll
            for (int e = 0; e < 4; ++e) pacc[mt][e] = 0.f;
        #pragma unroll
        for (int term = 0; term < 2; ++term)
            #pragma unroll
            for (int kt = 0; kt < 2; ++kt)
                #pragma unroll
                for (int mt = 0; mt < 2; ++mt)
                    mma16816(pacc[mt], aF[mt][kt],
                             bW[term][kt][0], bW[term][kt][1]);

        // lane%4==0 threads hold (row, o=0/1) and (row+8, o=0/1)
        char* sredBuf = smc + SM_SRED + (s & 1) * 2048;
        if ((lane & 3) == 0) {
            #pragma unroll
            for (int mt = 0; mt < 2; ++mt) {
                const int row = r00 + 16 * mt;
                *(float*)(sredBuf + (((row    ) * 2 + 0) * 4 + ng) * 4) = pacc[mt][0];
                *(float*)(sredBuf + (((row    ) * 2 + 1) * 4 + ng) * 4) = pacc[mt][1];
                *(float*)(sredBuf + (((row + 8) * 2 + 0) * 4 + ng) * 4) = pacc[mt][2];
                *(float*)(sredBuf + (((row + 8) * 2 + 1) * 4 + ng) * 4) = pacc[mt][3];
            }
        }
        __syncthreads();

        if (tid < 128) {
            const float4 v = *(const float4*)(sredBuf + tid * 16);
            float sum = (v.x + v.y) + (v.z + v.w);
            memout[tid] = fmaf(BETA, memout[tid], sum);
        }
    }

    // ---- epilogue ----
    if (tid < 128) {
        const int row = tid >> 1, o = tid & 1;
        const float v = o ? vy[0] : vx[0];
        out[((size_t)t * B_ + b0 + row) * 2 + o] = memout[tid] * v;
    }
}

// ---------------------------------------------------------------------------
extern "C" void kernel_launch(void* const* d_in, const int* in_sizes, int n_in,
                              void* d_out, int out_size) {
    const float* x    = (const float*)d_in[0];
    const float* Win  = (const float*)d_in[1];
    const float* Wh0  = (const float*)d_in[2];
    const float* Wout = (const float*)d_in[3];
    const float* vx   = (const float*)d_in[4];
    const float* vy   = (const float*)d_in[5];
    float* out = (float*)d_out;

    const int smem1 = (96 * 132 + 96 * 132) * 4;   // 101376 B
    const int smem2 = 129 * 128 * 4;               // 66048 B
    cudaFuncSetAttribute(k_gemm_in, cudaFuncAttributeMaxDynamicSharedMemorySize, smem1);
    cudaFuncSetAttribute(k_pl1,     cudaFuncAttributeMaxDynamicSharedMemorySize, smem2);
    cudaFuncSetAttribute(k_snn_b,   cudaFuncAttributeMaxDynamicSharedMemorySize, SM_TOTAL);

    k_gemm_in<<<(T_ * B_) / 128, 512, smem1>>>(x, Win);
    k_wsplit<<<32, 256>>>(Wh0);
    k_pl1<<<BH / 128, 128, smem2>>>();
    k_snn_b<<<T_ * 16, 256, SM_TOTAL>>>(Wout, vx, vy, out);
}